// round 13
// baseline (speedup 1.0000x reference)
#include <cuda_runtime.h>
#include <cstdint>

#define RFQ 16
#define NCHUNK 128
#define NB 4
#define NT 512
#define NGRID 128
#define TS 68
#define TILE_F 4368   // floats per tile buffer (64*68 + skew headroom)

typedef unsigned long long ull;

// ---- precomputed tables (setup kernel) ----
__device__ float VPg[12288];      // [3][64 vocab][64 j]  (b_ih + b_hh(r,z) folded)
__device__ float RVTg[64 * 193];  // [64 i][192 row], stride 193 (bank skew)
__device__ float ATg[64 * 65];    // [64 c][64 i], stride 65
__device__ float A0g[64];
__device__ float RV0g[192];

// smem offsets (floats)
#define OFF_RVT   0              // 12352
#define OFF_AT    12352          // 4160
#define OFF_A0    16512          // 64
#define OFF_RV0   16576          // 192
#define OFF_TILE  16768          // 8 * 4368 = 34944 (4 groups x 2 bufs)
#define OFF_HS    51712          // 4 * 128
#define OFF_QS    52224          // 4 * 64
#define OFF_ES    52480          // 4 * 64
#define OFF_RS    52736          // 4 * 64
#define OFF_TOK   52992          // 4 * 16 ints
#define SMEM_FLOATS 53056        // 212224 bytes

#define TROW(m) ((m) * TS + (((m) & 32) >> 1))   // +16 skew for rows 32..63

__device__ __forceinline__ void gbar(int id) {
    asm volatile("bar.sync %0, 128;" :: "r"(id) : "memory");
}
__device__ __forceinline__ float sigmoidf_(float x) {
    float e = __expf(-x);
    return __fdividef(1.f, 1.f + e);
}
__device__ __forceinline__ float tanhf_(float x) {
    float e = __expf(2.f * x);
    return 1.f - __fdividef(2.f, e + 1.f);
}
__device__ __forceinline__ ull pk(float a, float b) {
    ull r; asm("mov.b64 %0, {%1,%2};" : "=l"(r) : "f"(a), "f"(b)); return r;
}
__device__ __forceinline__ void fma2(ull& d, ull a, ull b) {
    asm("fma.rn.f32x2 %0, %1, %2, %0;" : "+l"(d) : "l"(a), "l"(b));
}
__device__ __forceinline__ float2 upk(ull a) {
    float2 f; asm("mov.b64 {%0,%1}, %2;" : "=f"(f.x), "=f"(f.y) : "l"(a)); return f;
}
__device__ __forceinline__ uint32_t s2u(const void* p) {
    return (uint32_t)__cvta_generic_to_shared(p);
}
__device__ __forceinline__ void cp16(uint32_t d, const float4* s) {
    asm volatile("cp.async.cg.shared.global [%0], [%1], 16;" :: "r"(d), "l"(s));
}
__device__ __forceinline__ void cpcommit() { asm volatile("cp.async.commit_group;"); }
template <int N> __device__ __forceinline__ void cpwait() {
    asm volatile("cp.async.wait_group %0;" :: "n"(N) : "memory");
}

// issue one 64x64 tile copy (8 x cp.async.16 per thread, 128 threads/group)
__device__ __forceinline__ void issue_tile(uint32_t tb_bytes, const float4* mt4, int tid_b) {
#pragma unroll
    for (int it = 0; it < 8; it++) {
        const int e4 = it * 128 + tid_b;
        const int r = e4 >> 4, c4 = e4 & 15;
        cp16(tb_bytes + (uint32_t)((TROW(r) + c4 * 4) * 4), mt4 + e4);
    }
    cpcommit();
}

// ---- setup kernel: fold all token/attention algebra once ----
__global__ void setup_k(const float* __restrict__ embed_w, const float* __restrict__ w_ih,
                        const float* __restrict__ b_ih, const float* __restrict__ b_hh,
                        const float* __restrict__ key_w, const float* __restrict__ val_w,
                        const float* __restrict__ val_b, const float* __restrict__ query_w,
                        const float* __restrict__ query_b)
{
    const int idx = blockIdx.x * 256 + threadIdx.x;
    if (idx < 12288) {
        // VP[g][v][jj] = emb[v].W_ih_x[row] + b_ih[row] + (g<2 ? b_hh[row] : 0)
        const int g = idx >> 12, v = (idx >> 6) & 63, jj = idx & 63;
        const int row = g * 64 + jj;
        float acc = b_ih[row] + (g < 2 ? b_hh[row] : 0.f);
#pragma unroll 8
        for (int c = 0; c < 64; c++) acc = fmaf(embed_w[v * 64 + c], w_ih[row * 128 + c], acc);
        VPg[idx] = acc;
    } else if (idx < 24576) {
        // RVT[i][row] = sum_k W_ih_ret[row][k] * val_w[k][i]   (stride-193)
        const int t = idx - 12288;
        const int i = t / 192, row = t % 192;
        float acc = 0.f;
#pragma unroll 8
        for (int k = 0; k < 64; k++) acc = fmaf(w_ih[row * 128 + 64 + k], val_w[k * 64 + i], acc);
        RVTg[i * 193 + row] = acc;
    } else if (idx < 28672) {
        // AT[c][i] = scale * sum_k key_w[k][i]*query_w[k][c]   (stride-65)
        const int t = idx - 24576;
        const int c = t >> 6, i = t & 63;
        float acc = 0.f;
#pragma unroll 8
        for (int k = 0; k < 64; k++) acc = fmaf(key_w[k * 64 + i], query_w[k * 64 + c], acc);
        ATg[c * 65 + i] = acc * 0.125f;
    } else if (idx < 28736) {
        const int i = idx - 28672;
        float acc = 0.f;
#pragma unroll 8
        for (int k = 0; k < 64; k++) acc = fmaf(key_w[k * 64 + i], query_b[k], acc);
        A0g[i] = acc * 0.125f;
    } else if (idx < 28928) {
        const int row = idx - 28736;
        float acc = 0.f;
#pragma unroll 8
        for (int k = 0; k < 64; k++) acc = fmaf(w_ih[row * 128 + 64 + k], val_b[k], acc);
        RV0g[row] = acc;
    }
}

__global__ void __launch_bounds__(NT, 1) ffm_kernel(
    const int*   __restrict__ seq,
    const float* __restrict__ memory,
    const float* __restrict__ w_hh,
    const float* __restrict__ b_hh,
    const float* __restrict__ head_w,
    const float* __restrict__ head_b,
    float* __restrict__ out)
{
    extern __shared__ float sm[];
    float* RVT = sm + OFF_RVT;
    float* AT  = sm + OFF_AT;
    float* A0  = sm + OFF_A0;
    float* RV0 = sm + OFF_RV0;

    const int tid   = threadIdx.x;
    const int tid_b = tid & 127;          // within batch group
    const int j     = tid_b >> 1;         // gate row 0..63
    const int p     = tid_b & 1;          // i-half: [32p, 32p+32)
    const int bl    = tid >> 7;           // batch group 0..3
    const int bg    = blockIdx.x * NB + bl;
    const int barid = bl + 1;

    // ---- copy tables into shared ----
    for (int e = tid; e < 12352; e += NT) RVT[e] = RVTg[e];
    for (int e = tid; e < 4160;  e += NT) AT[e]  = ATg[e];
    if (tid < 64)  A0[tid]  = A0g[tid];
    if (tid < 192) RV0[tid] = RV0g[tid];

    float* TILE0 = sm + OFF_TILE + (bl * 2 + 0) * TILE_F;
    float* TILE1 = sm + OFF_TILE + (bl * 2 + 1) * TILE_F;
    const uint32_t u0 = s2u(TILE0), u1 = s2u(TILE1);
    float* HSb = sm + OFF_HS + bl * 128;
    float* QSb = sm + OFF_QS + bl * 64;
    float* ESb = sm + OFF_ES + bl * 64;
    float* RSb = sm + OFF_RS + bl * 64;
    int*   TOKb = (int*)(sm + OFF_TOK) + bl * 16;

    if (!p) HSb[j] = 0.f;

    // ---- load W_hh half-rows into registers (once, forever) ----
    ull wr2[16], wz2[16], wn2[16];
    {
        const float4* wh4 = (const float4*)w_hh;
        const int base = (j * 64 + 32 * p) >> 2;
#pragma unroll
        for (int k = 0; k < 8; k++) {
            float4 a = wh4[base + k];
            float4 b = wh4[base + 1024 + k];
            float4 c = wh4[base + 2048 + k];
            wr2[2 * k] = pk(a.x, a.y); wr2[2 * k + 1] = pk(a.z, a.w);
            wz2[2 * k] = pk(b.x, b.y); wz2[2 * k + 1] = pk(b.z, b.w);
            wn2[2 * k] = pk(c.x, c.y); wn2[2 * k + 1] = pk(c.z, c.w);
        }
    }
    const float bhn = b_hh[128 + j];

    float h = 0.f;
    const float4* mt4 = (const float4*)(memory + (size_t)bg * (256 * 64));
    const int* seqb = seq + (size_t)bg * 2048;
    __syncthreads();

    // prefetch tiles 0,1 of chunk 0
    issue_tile(u0, mt4, tid_b);
    issue_tile(u1, mt4 + 1024, tid_b);

#pragma unroll 1
    for (int ch = 0; ch < NCHUNK; ch++) {
        if (tid_b < 16) TOKb[tid_b] = seqb[ch * RFQ + tid_b];
        // query: qt[j] partial over c-half (4 chains), shfl-combined
        {
            float q0 = 0.f, q1 = 0.f, q2 = 0.f, q3 = 0.f;
#pragma unroll
            for (int ci = 0; ci < 32; ci += 4) {
                const int c0 = 32 * p + ((ci + 16 * p) & 31);
                const int c1 = 32 * p + ((ci + 1 + 16 * p) & 31);
                const int c2 = 32 * p + ((ci + 2 + 16 * p) & 31);
                const int c3 = 32 * p + ((ci + 3 + 16 * p) & 31);
                q0 = fmaf(AT[c0 * 65 + j], HSb[c0], q0);
                q1 = fmaf(AT[c1 * 65 + j], HSb[c1], q1);
                q2 = fmaf(AT[c2 * 65 + j], HSb[c2], q2);
                q3 = fmaf(AT[c3 * 65 + j], HSb[c3], q3);
            }
            float qt = (q0 + q1) + (q2 + q3);
            qt += __shfl_xor_sync(~0u, qt, 1);
            if (!p) QSb[j] = qt + A0[j];
        }

        // ---- attention: 4 tiles, max-free softmax (|score| provably <= ~36) ----
        // macc/D accumulate in 4 chains across all tiles; single normalization at end.
        float mc0 = 0.f, mc1 = 0.f, mc2 = 0.f, mc3 = 0.f;
        float dd0 = 0.f, dd1 = 0.f, dd2 = 0.f, dd3 = 0.f;
#pragma unroll
        for (int t = 0; t < 4; t++) {
            if (t < 3) cpwait<1>(); else cpwait<0>();
            gbar(barid);
            const float* tb = (t & 1) ? TILE1 : TILE0;
            // score row j: 2 fma2 chains, p-rotated columns (conflict-free)
            float s;
            {
                ull s2a = 0ull, s2b = 0ull;
                const float* rowp = tb + TROW(j);
#pragma unroll
                for (int k = 0; k < 8; k++) {
                    const int kk = (k + 4 * p) & 7;
                    const int col = 32 * p + 4 * kk;
                    const float4 qv = *(const float4*)(QSb + col);
                    const float4 rv = *(const float4*)(rowp + col);
                    ull& chain = (k & 1) ? s2b : s2a;
                    fma2(chain, pk(qv.x, qv.y), pk(rv.x, rv.y));
                    fma2(chain, pk(qv.z, qv.w), pk(rv.z, rv.w));
                }
                const float2 sf = upk(s2a), sg = upk(s2b);
                s = (sf.x + sf.y) + (sg.x + sg.y);
            }
            s += __shfl_xor_sync(~0u, s, 1);
            const float e = __expf(s);          // safe: |s| bounded, no max shift needed
            if (!p) ESb[j] = e;
            gbar(barid);
            // weighted accumulation over this tile's 32-row half (4 chains)
            const float* colp = tb + TROW(32 * p) + j;
            const float* ep = ESb + 32 * p;
#pragma unroll
            for (int mi = 0; mi < 32; mi += 4) {
                const float e0 = ep[mi], e1 = ep[mi + 1], e2 = ep[mi + 2], e3 = ep[mi + 3];
                mc0 = fmaf(e0, colp[(mi + 0) * TS], mc0); dd0 += e0;
                mc1 = fmaf(e1, colp[(mi + 1) * TS], mc1); dd1 += e1;
                mc2 = fmaf(e2, colp[(mi + 2) * TS], mc2); dd2 += e2;
                mc3 = fmaf(e3, colp[(mi + 3) * TS], mc3); dd3 += e3;
            }
            gbar(barid);
            // refill the buffer just consumed with tile t+2
            if (t < 2) issue_tile((t & 1) ? u1 : u0, mt4 + (t + 2) * 1024, tid_b);
        }
        {
            float macc = (mc0 + mc1) + (mc2 + mc3);
            float D    = (dd0 + dd1) + (dd2 + dd3);
            macc += __shfl_xor_sync(~0u, macc, 1);
            D    += __shfl_xor_sync(~0u, D, 1);
            if (!p) RSb[j] = macc / D;
        }
        gbar(barid);

        // prefetch next chunk's tiles 0,1 (memory is chunk-invariant; overlaps GRU)
        if (ch != NCHUNK - 1) {
            issue_tile(u0, mt4, tid_b);
            issue_tile(u1, mt4 + 1024, tid_b);
        }

        // r_proj partials over i-half (2 chains per gate), shfl-combined
        float rr0 = 0.f, rr1 = 0.f, rz0 = 0.f, rz1 = 0.f, rn0 = 0.f, rn1 = 0.f;
#pragma unroll
        for (int ii = 0; ii < 32; ii += 2) {
            const int i0 = 32 * p + ((ii + 16 * p) & 31);
            const int i1 = 32 * p + ((ii + 1 + 16 * p) & 31);
            const float rv0 = RSb[i0], rv1 = RSb[i1];
            const float* rt0 = RVT + i0 * 193;
            const float* rt1 = RVT + i1 * 193;
            rr0 = fmaf(rt0[j], rv0, rr0);        rr1 = fmaf(rt1[j], rv1, rr1);
            rz0 = fmaf(rt0[64 + j], rv0, rz0);   rz1 = fmaf(rt1[64 + j], rv1, rz1);
            rn0 = fmaf(rt0[128 + j], rv0, rn0);  rn1 = fmaf(rt1[128 + j], rv1, rn1);
        }
        float rp_r = rr0 + rr1, rp_z = rz0 + rz1, rp_n = rn0 + rn1;
        rp_r += __shfl_xor_sync(~0u, rp_r, 1);
        rp_z += __shfl_xor_sync(~0u, rp_z, 1);
        rp_n += __shfl_xor_sync(~0u, rp_n, 1);
        rp_r += RV0[j]; rp_z += RV0[64 + j]; rp_n += RV0[128 + j];

        // ---- 16 GRU steps: split-K fma2 dots (2 chains/gate) + shfl combine ----
        int curl = 0;
#pragma unroll 1
        for (int st = 0; st < RFQ; st++) {
            const int tok = TOKb[st];
            const float* vp = VPg + tok * 64 + j;
            const float gxr = vp[0] + rp_r;
            const float gxz = vp[4096] + rp_z;
            const float gxn = vp[8192] + rp_n;
            const float4* h4 = (const float4*)(HSb + curl * 64 + 32 * p);
            ull ar0 = 0ull, ar1 = 0ull, az0 = 0ull, az1 = 0ull, an0 = 0ull, an1 = 0ull;
#pragma unroll
            for (int k = 0; k < 8; k++) {
                const float4 hv = h4[k];
                const ull h01 = pk(hv.x, hv.y), h23 = pk(hv.z, hv.w);
                ull& cr = (k & 1) ? ar1 : ar0;
                ull& cz = (k & 1) ? az1 : az0;
                ull& cn = (k & 1) ? an1 : an0;
                fma2(cr, wr2[2 * k], h01); fma2(cz, wz2[2 * k], h01); fma2(cn, wn2[2 * k], h01);
                fma2(cr, wr2[2 * k + 1], h23); fma2(cz, wz2[2 * k + 1], h23); fma2(cn, wn2[2 * k + 1], h23);
            }
            float2 f, g;
            f = upk(ar0); g = upk(ar1); float ars = (f.x + f.y) + (g.x + g.y);
            f = upk(az0); g = upk(az1); float azs = (f.x + f.y) + (g.x + g.y);
            f = upk(an0); g = upk(an1); float ans = (f.x + f.y) + (g.x + g.y);
            ars += __shfl_xor_sync(~0u, ars, 1);
            azs += __shfl_xor_sync(~0u, azs, 1);
            ans += __shfl_xor_sync(~0u, ans, 1);
            const float r = sigmoidf_(gxr + ars);
            const float z = sigmoidf_(gxz + azs);
            const float n = tanhf_(gxn + r * (ans + bhn));
            const float hn = fmaf(z, h - n, n);
            if (!p) HSb[(curl ^ 1) * 64 + j] = hn;
            h = hn;
            gbar(barid);
            curl ^= 1;
        }
    }

    // ---- head (h ends in HS buffer 0) ----
    {
        float o = 0.f;
        const float4* hw4 = (const float4*)(head_w + j * 64 + 32 * p);
        const float4* hf4 = (const float4*)(HSb + 32 * p);
#pragma unroll
        for (int k = 0; k < 8; k++) {
            const float4 w = hw4[k], v = hf4[k];
            o = fmaf(w.x, v.x, o); o = fmaf(w.y, v.y, o);
            o = fmaf(w.z, v.z, o); o = fmaf(w.w, v.w, o);
        }
        o += __shfl_xor_sync(~0u, o, 1);
        if (!p) out[(size_t)bg * 64 + j] = o + head_b[j];
    }
}

extern "C" void kernel_launch(void* const* d_in, const int* in_sizes, int n_in,
                              void* d_out, int out_size) {
    const int*   seq      = (const int*)  d_in[0];
    const float* memory   = (const float*)d_in[1];
    const float* embed_w  = (const float*)d_in[2];
    const float* w_ih     = (const float*)d_in[3];
    const float* w_hh     = (const float*)d_in[4];
    const float* b_ih     = (const float*)d_in[5];
    const float* b_hh     = (const float*)d_in[6];
    const float* key_w    = (const float*)d_in[7];
    const float* key_b    = (const float*)d_in[8];   // cancels in softmax
    const float* val_w    = (const float*)d_in[9];
    const float* val_b    = (const float*)d_in[10];
    const float* query_w  = (const float*)d_in[11];
    const float* query_b  = (const float*)d_in[12];
    const float* head_w   = (const float*)d_in[13];
    const float* head_b   = (const float*)d_in[14];
    (void)key_b;

    setup_k<<<113, 256>>>(embed_w, w_ih, b_ih, b_hh, key_w, val_w, val_b, query_w, query_b);

    const size_t shmem = (size_t)SMEM_FLOATS * sizeof(float);
    cudaFuncSetAttribute(ffm_kernel, cudaFuncAttributeMaxDynamicSharedMemorySize, (int)shmem);
    ffm_kernel<<<NGRID, NT, shmem>>>(seq, memory, w_hh, b_hh, head_w, head_b, (float*)d_out);
}

// round 14
// speedup vs baseline: 1.0248x; 1.0248x over previous
#include <cuda_runtime.h>
#include <cstdint>

#define RFQ 16
#define NCHUNK 128
#define NT 256
#define NGRID 128
#define TS 68
#define TILE_F 4368

typedef unsigned long long ull;

// ---- precomputed tables (setup kernel) ----
__device__ float VPg[12288];      // [3][64 vocab][64 j]  (b_ih + b_hh(r,z) folded)
__device__ float RVTg[64 * 193];  // [64 i][192 row], stride 193
__device__ float ATg[64 * 65];    // [64 c][64 i], stride 65
__device__ float A0g[64];
__device__ float RV0g[192];

// smem offsets (floats)
#define OFF_RVT   0              // 12352
#define OFF_AT    12352          // 4160
#define OFF_A0    16512          // 64
#define OFF_RV0   16576          // 192
#define OFF_TILE  16768          // 8 * 4368 : [group][batch][dbuf]
#define OFF_HS    51712          // 4 * 128
#define OFF_QS    52224          // 4 * 64
#define OFF_ES    52480          // 4 * 64
#define OFF_RS    52736          // 4 * 64
#define OFF_TOK   52992          // 64 ints
#define SMEM_FLOATS 53056        // 212224 bytes

#define TROW(m) ((m) * TS + (((m) & 32) >> 1))

__device__ __forceinline__ void gbar(int id) {
    asm volatile("bar.sync %0, 128;" :: "r"(id) : "memory");
}
__device__ __forceinline__ float sigmoidf_(float x) {
    float e = __expf(-x);
    return __fdividef(1.f, 1.f + e);
}
__device__ __forceinline__ float tanhf_(float x) {
    float e = __expf(2.f * x);
    return 1.f - __fdividef(2.f, e + 1.f);
}
__device__ __forceinline__ ull pk(float a, float b) {
    ull r; asm("mov.b64 %0, {%1,%2};" : "=l"(r) : "f"(a), "f"(b)); return r;
}
__device__ __forceinline__ void fma2(ull& d, ull a, ull b) {
    asm("fma.rn.f32x2 %0, %1, %2, %0;" : "+l"(d) : "l"(a), "l"(b));
}
__device__ __forceinline__ float2 upk(ull a) {
    float2 f; asm("mov.b64 {%0,%1}, %2;" : "=f"(f.x), "=f"(f.y) : "l"(a)); return f;
}
__device__ __forceinline__ uint32_t s2u(const void* p) {
    return (uint32_t)__cvta_generic_to_shared(p);
}
__device__ __forceinline__ void cp16(uint32_t d, const float4* s) {
    asm volatile("cp.async.cg.shared.global [%0], [%1], 16;" :: "r"(d), "l"(s));
}
__device__ __forceinline__ void cpcommit() { asm volatile("cp.async.commit_group;"); }
template <int N> __device__ __forceinline__ void cpwait() {
    asm volatile("cp.async.wait_group %0;" :: "n"(N) : "memory");
}

// issue both batches' 64x64 tiles for one double-buffer slot; ONE commit group
__device__ __forceinline__ void issue2(uint32_t d0, uint32_t d1,
                                       const float4* m0, const float4* m1, int tid_b) {
#pragma unroll
    for (int it = 0; it < 8; it++) {
        const int e4 = it * 128 + tid_b;
        const int r = e4 >> 4, c4 = e4 & 15;
        const uint32_t off = (uint32_t)((TROW(r) + c4 * 4) * 4);
        cp16(d0 + off, m0 + e4);
        cp16(d1 + off, m1 + e4);
    }
    cpcommit();
}

// ---- setup kernel: fold all token/attention algebra once ----
__global__ void setup_k(const float* __restrict__ embed_w, const float* __restrict__ w_ih,
                        const float* __restrict__ b_ih, const float* __restrict__ b_hh,
                        const float* __restrict__ key_w, const float* __restrict__ val_w,
                        const float* __restrict__ val_b, const float* __restrict__ query_w,
                        const float* __restrict__ query_b)
{
    const int idx = blockIdx.x * 256 + threadIdx.x;
    if (idx < 12288) {
        const int g = idx >> 12, v = (idx >> 6) & 63, jj = idx & 63;
        const int row = g * 64 + jj;
        float acc = b_ih[row] + (g < 2 ? b_hh[row] : 0.f);
#pragma unroll 8
        for (int c = 0; c < 64; c++) acc = fmaf(embed_w[v * 64 + c], w_ih[row * 128 + c], acc);
        VPg[idx] = acc;
    } else if (idx < 24576) {
        const int t = idx - 12288;
        const int i = t / 192, row = t % 192;
        float acc = 0.f;
#pragma unroll 8
        for (int k = 0; k < 64; k++) acc = fmaf(w_ih[row * 128 + 64 + k], val_w[k * 64 + i], acc);
        RVTg[i * 193 + row] = acc;
    } else if (idx < 28672) {
        const int t = idx - 24576;
        const int c = t >> 6, i = t & 63;
        float acc = 0.f;
#pragma unroll 8
        for (int k = 0; k < 64; k++) acc = fmaf(key_w[k * 64 + i], query_w[k * 64 + c], acc);
        ATg[c * 65 + i] = acc * 0.125f;
    } else if (idx < 28736) {
        const int i = idx - 28672;
        float acc = 0.f;
#pragma unroll 8
        for (int k = 0; k < 64; k++) acc = fmaf(key_w[k * 64 + i], query_b[k], acc);
        A0g[i] = acc * 0.125f;
    } else if (idx < 28928) {
        const int row = idx - 28736;
        float acc = 0.f;
#pragma unroll 8
        for (int k = 0; k < 64; k++) acc = fmaf(w_ih[row * 128 + 64 + k], val_b[k], acc);
        RV0g[row] = acc;
    }
}

__global__ void __launch_bounds__(NT, 1) ffm_kernel(
    const int*   __restrict__ seq,
    const float* __restrict__ memory,
    const float* __restrict__ w_hh,
    const float* __restrict__ b_hh,
    const float* __restrict__ head_w,
    const float* __restrict__ head_b,
    float* __restrict__ out)
{
    extern __shared__ float sm[];
    float* RVT = sm + OFF_RVT;
    float* AT  = sm + OFF_AT;
    float* A0  = sm + OFF_A0;
    float* RV0 = sm + OFF_RV0;

    const int tid   = threadIdx.x;
    const int tid_b = tid & 127;          // within group
    const int j     = tid_b >> 1;         // gate row 0..63
    const int p     = tid_b & 1;          // i-half
    const int gl    = tid >> 7;           // group 0..1 (2 batches each)
    const int bg0   = blockIdx.x * 4 + gl * 2;
    const int bg1   = bg0 + 1;
    const int barid = gl + 1;

    for (int e = tid; e < 12352; e += NT) RVT[e] = RVTg[e];
    for (int e = tid; e < 4160;  e += NT) AT[e]  = ATg[e];
    if (tid < 64)  A0[tid]  = A0g[tid];
    if (tid < 192) RV0[tid] = RV0g[tid];

    float* TILEg = sm + OFF_TILE + gl * 4 * TILE_F;   // [batch][dbuf]
    const uint32_t u00 = s2u(TILEg), u01 = s2u(TILEg + TILE_F);
    const uint32_t u10 = s2u(TILEg + 2 * TILE_F), u11 = s2u(TILEg + 3 * TILE_F);
    float* HS0 = sm + OFF_HS + (gl * 2 + 0) * 128;
    float* HS1 = sm + OFF_HS + (gl * 2 + 1) * 128;
    float* QS0 = sm + OFF_QS + (gl * 2 + 0) * 64;
    float* QS1 = sm + OFF_QS + (gl * 2 + 1) * 64;
    float* ES0 = sm + OFF_ES + (gl * 2 + 0) * 64;
    float* ES1 = sm + OFF_ES + (gl * 2 + 1) * 64;
    float* RS0 = sm + OFF_RS + (gl * 2 + 0) * 64;
    float* RS1 = sm + OFF_RS + (gl * 2 + 1) * 64;
    int* TOK0 = (int*)(sm + OFF_TOK) + (gl * 2 + 0) * 16;
    int* TOK1 = (int*)(sm + OFF_TOK) + (gl * 2 + 1) * 16;

    if (!p) { HS0[j] = 0.f; HS1[j] = 0.f; }

    // ---- W_hh half-rows in registers, shared across both batches ----
    ull wr2[16], wz2[16], wn2[16];
    {
        const float4* wh4 = (const float4*)w_hh;
        const int base = (j * 64 + 32 * p) >> 2;
#pragma unroll
        for (int k = 0; k < 8; k++) {
            float4 a = wh4[base + k];
            float4 b = wh4[base + 1024 + k];
            float4 c = wh4[base + 2048 + k];
            wr2[2 * k] = pk(a.x, a.y); wr2[2 * k + 1] = pk(a.z, a.w);
            wz2[2 * k] = pk(b.x, b.y); wz2[2 * k + 1] = pk(b.z, b.w);
            wn2[2 * k] = pk(c.x, c.y); wn2[2 * k + 1] = pk(c.z, c.w);
        }
    }
    const float bhn = b_hh[128 + j];

    float h0 = 0.f, h1 = 0.f;
    const float4* mt0 = (const float4*)(memory + (size_t)bg0 * (256 * 64));
    const float4* mt1 = (const float4*)(memory + (size_t)bg1 * (256 * 64));
    const int* seqb0 = seq + (size_t)bg0 * 2048;
    const int* seqb1 = seq + (size_t)bg1 * 2048;
    __syncthreads();

    issue2(u00, u10, mt0, mt1, tid_b);               // slot 0 : tile 0
    issue2(u01, u11, mt0 + 1024, mt1 + 1024, tid_b); // slot 1 : tile 1

#pragma unroll 1
    for (int ch = 0; ch < NCHUNK; ch++) {
        if (tid_b < 16) TOK0[tid_b] = seqb0[ch * RFQ + tid_b];
        else if (tid_b < 32) TOK1[tid_b - 16] = seqb1[ch * RFQ + tid_b - 16];

        // query: AT loads shared across batches
        {
            float qa0 = 0.f, qb0 = 0.f, qa1 = 0.f, qb1 = 0.f;
#pragma unroll
            for (int ci = 0; ci < 32; ci += 2) {
                const int c0 = 32 * p + ((ci + 16 * p) & 31);
                const int c1 = 32 * p + ((ci + 1 + 16 * p) & 31);
                const float aa = AT[c0 * 65 + j], ab = AT[c1 * 65 + j];
                qa0 = fmaf(aa, HS0[c0], qa0); qa1 = fmaf(aa, HS1[c0], qa1);
                qb0 = fmaf(ab, HS0[c1], qb0); qb1 = fmaf(ab, HS1[c1], qb1);
            }
            float qt0 = qa0 + qb0, qt1 = qa1 + qb1;
            qt0 += __shfl_xor_sync(~0u, qt0, 1);
            qt1 += __shfl_xor_sync(~0u, qt1, 1);
            if (!p) { QS0[j] = qt0 + A0[j]; QS1[j] = qt1 + A0[j]; }
        }

        // ---- attention: 4 tiles, max-free softmax, both batches interleaved ----
        float mc00 = 0.f, mc01 = 0.f, mc10 = 0.f, mc11 = 0.f;
        float dd00 = 0.f, dd01 = 0.f, dd10 = 0.f, dd11 = 0.f;
#pragma unroll
        for (int t = 0; t < 4; t++) {
            if (t < 3) cpwait<1>(); else cpwait<0>();
            gbar(barid);
            const float* tb0 = TILEg + (t & 1) * TILE_F;
            const float* tb1 = TILEg + (2 + (t & 1)) * TILE_F;
            // scores (one fma2 chain per batch)
            float s0, s1;
            {
                ull c0 = 0ull, c1 = 0ull;
                const float* r0 = tb0 + TROW(j);
                const float* r1 = tb1 + TROW(j);
#pragma unroll
                for (int k = 0; k < 8; k++) {
                    const int kk = (k + 4 * p) & 7;
                    const int col = 32 * p + 4 * kk;
                    const float4 q0 = *(const float4*)(QS0 + col);
                    const float4 v0 = *(const float4*)(r0 + col);
                    fma2(c0, pk(q0.x, q0.y), pk(v0.x, v0.y));
                    fma2(c0, pk(q0.z, q0.w), pk(v0.z, v0.w));
                    const float4 q1 = *(const float4*)(QS1 + col);
                    const float4 v1 = *(const float4*)(r1 + col);
                    fma2(c1, pk(q1.x, q1.y), pk(v1.x, v1.y));
                    fma2(c1, pk(q1.z, q1.w), pk(v1.z, v1.w));
                }
                const float2 f0 = upk(c0), f1 = upk(c1);
                s0 = f0.x + f0.y; s1 = f1.x + f1.y;
            }
            s0 += __shfl_xor_sync(~0u, s0, 1);
            s1 += __shfl_xor_sync(~0u, s1, 1);
            const float e0 = __expf(s0);   // |score| provably bounded -> no max shift
            const float e1 = __expf(s1);
            if (!p) { ES0[j] = e0; ES1[j] = e1; }
            gbar(barid);
            const float* cp0 = tb0 + TROW(32 * p) + j;
            const float* cp1 = tb1 + TROW(32 * p) + j;
            const float* ep0 = ES0 + 32 * p;
            const float* ep1 = ES1 + 32 * p;
#pragma unroll
            for (int mi = 0; mi < 32; mi += 2) {
                const float ea0 = ep0[mi], eb0 = ep0[mi + 1];
                mc00 = fmaf(ea0, cp0[mi * TS], mc00);       dd00 += ea0;
                mc01 = fmaf(eb0, cp0[(mi + 1) * TS], mc01); dd01 += eb0;
                const float ea1 = ep1[mi], eb1 = ep1[mi + 1];
                mc10 = fmaf(ea1, cp1[mi * TS], mc10);       dd10 += ea1;
                mc11 = fmaf(eb1, cp1[(mi + 1) * TS], mc11); dd11 += eb1;
            }
            gbar(barid);
            if (t < 2) issue2((t & 1) ? u01 : u00, (t & 1) ? u11 : u10,
                              mt0 + (t + 2) * 1024, mt1 + (t + 2) * 1024, tid_b);
        }
        {
            float m0 = mc00 + mc01, D0 = dd00 + dd01;
            float m1 = mc10 + mc11, D1 = dd10 + dd11;
            m0 += __shfl_xor_sync(~0u, m0, 1); D0 += __shfl_xor_sync(~0u, D0, 1);
            m1 += __shfl_xor_sync(~0u, m1, 1); D1 += __shfl_xor_sync(~0u, D1, 1);
            if (!p) { RS0[j] = m0 / D0; RS1[j] = m1 / D1; }
        }
        gbar(barid);

        // prefetch next chunk's tiles 0,1 (overlaps GRU)
        if (ch != NCHUNK - 1) {
            issue2(u00, u10, mt0, mt1, tid_b);
            issue2(u01, u11, mt0 + 1024, mt1 + 1024, tid_b);
        }

        // r_proj: RVT loads shared across batches
        float rr0 = 0.f, rz0 = 0.f, rn0 = 0.f, rr1 = 0.f, rz1 = 0.f, rn1 = 0.f;
#pragma unroll
        for (int ii = 0; ii < 32; ii++) {
            const int i = 32 * p + ((ii + 16 * p) & 31);
            const float rv0 = RS0[i], rv1 = RS1[i];
            const float* rt = RVT + i * 193;
            const float tr = rt[j], tz = rt[64 + j], tn = rt[128 + j];
            rr0 = fmaf(tr, rv0, rr0); rr1 = fmaf(tr, rv1, rr1);
            rz0 = fmaf(tz, rv0, rz0); rz1 = fmaf(tz, rv1, rz1);
            rn0 = fmaf(tn, rv0, rn0); rn1 = fmaf(tn, rv1, rn1);
        }
        rr0 += __shfl_xor_sync(~0u, rr0, 1); rz0 += __shfl_xor_sync(~0u, rz0, 1);
        rn0 += __shfl_xor_sync(~0u, rn0, 1);
        rr1 += __shfl_xor_sync(~0u, rr1, 1); rz1 += __shfl_xor_sync(~0u, rz1, 1);
        rn1 += __shfl_xor_sync(~0u, rn1, 1);
        const float rp_r0 = rr0 + RV0[j], rp_z0 = rz0 + RV0[64 + j], rp_n0 = rn0 + RV0[128 + j];
        const float rp_r1 = rr1 + RV0[j], rp_z1 = rz1 + RV0[64 + j], rp_n1 = rn1 + RV0[128 + j];

        // ---- 16 GRU steps, 2 batches per thread, vp prefetched 1 step ahead ----
        int curl = 0;
        float v0r, v0z, v0n, v1r, v1z, v1n;
        {
            const int t0 = TOK0[0], t1 = TOK1[0];
            v0r = VPg[t0 * 64 + j]; v0z = VPg[4096 + t0 * 64 + j]; v0n = VPg[8192 + t0 * 64 + j];
            v1r = VPg[t1 * 64 + j]; v1z = VPg[4096 + t1 * 64 + j]; v1n = VPg[8192 + t1 * 64 + j];
        }
#pragma unroll 1
        for (int st = 0; st < RFQ; st++) {
            // prefetch next step's vp (clamped index keeps it branch-uniform)
            const int st1 = (st < RFQ - 1) ? st + 1 : st;
            const int nt0 = TOK0[st1], nt1 = TOK1[st1];
            const float n0r = VPg[nt0 * 64 + j], n0z = VPg[4096 + nt0 * 64 + j], n0n = VPg[8192 + nt0 * 64 + j];
            const float n1r = VPg[nt1 * 64 + j], n1z = VPg[4096 + nt1 * 64 + j], n1n = VPg[8192 + nt1 * 64 + j];

            const ulonglong2* h40 = (const ulonglong2*)(HS0 + curl * 64 + 32 * p);
            const ulonglong2* h41 = (const ulonglong2*)(HS1 + curl * 64 + 32 * p);
            ull ar0 = 0ull, az0 = 0ull, an0 = 0ull, ar1 = 0ull, az1 = 0ull, an1 = 0ull;
#pragma unroll
            for (int k = 0; k < 8; k++) {
                const ulonglong2 ha = h40[k];
                const ulonglong2 hb = h41[k];
                fma2(ar0, wr2[2 * k], ha.x);     fma2(az0, wz2[2 * k], ha.x);     fma2(an0, wn2[2 * k], ha.x);
                fma2(ar0, wr2[2 * k + 1], ha.y); fma2(az0, wz2[2 * k + 1], ha.y); fma2(an0, wn2[2 * k + 1], ha.y);
                fma2(ar1, wr2[2 * k], hb.x);     fma2(az1, wz2[2 * k], hb.x);     fma2(an1, wn2[2 * k], hb.x);
                fma2(ar1, wr2[2 * k + 1], hb.y); fma2(az1, wz2[2 * k + 1], hb.y); fma2(an1, wn2[2 * k + 1], hb.y);
            }
            float2 f;
            f = upk(ar0); float sr0 = f.x + f.y; sr0 += __shfl_xor_sync(~0u, sr0, 1);
            f = upk(az0); float sz0 = f.x + f.y; sz0 += __shfl_xor_sync(~0u, sz0, 1);
            f = upk(an0); float sn0 = f.x + f.y; sn0 += __shfl_xor_sync(~0u, sn0, 1);
            f = upk(ar1); float sr1 = f.x + f.y; sr1 += __shfl_xor_sync(~0u, sr1, 1);
            f = upk(az1); float sz1 = f.x + f.y; sz1 += __shfl_xor_sync(~0u, sz1, 1);
            f = upk(an1); float sn1 = f.x + f.y; sn1 += __shfl_xor_sync(~0u, sn1, 1);

            const float r0 = sigmoidf_(v0r + rp_r0 + sr0);
            const float z0 = sigmoidf_(v0z + rp_z0 + sz0);
            const float nn0 = tanhf_(v0n + rp_n0 + r0 * (sn0 + bhn));
            const float hn0 = fmaf(z0, h0 - nn0, nn0);
            const float r1 = sigmoidf_(v1r + rp_r1 + sr1);
            const float z1 = sigmoidf_(v1z + rp_z1 + sz1);
            const float nn1 = tanhf_(v1n + rp_n1 + r1 * (sn1 + bhn));
            const float hn1 = fmaf(z1, h1 - nn1, nn1);
            if (!p) {
                HS0[(curl ^ 1) * 64 + j] = hn0;
                HS1[(curl ^ 1) * 64 + j] = hn1;
            }
            h0 = hn0; h1 = hn1;
            gbar(barid);
            curl ^= 1;
            v0r = n0r; v0z = n0z; v0n = n0n;
            v1r = n1r; v1z = n1z; v1n = n1n;
        }
    }

    // ---- head (h ends in HS buffer 0; head_w loads shared) ----
    {
        float o0 = 0.f, o1 = 0.f;
        const float4* hw4 = (const float4*)(head_w + j * 64 + 32 * p);
        const float4* f0 = (const float4*)(HS0 + 32 * p);
        const float4* f1 = (const float4*)(HS1 + 32 * p);
#pragma unroll
        for (int k = 0; k < 8; k++) {
            const float4 w = hw4[k];
            const float4 a = f0[k], b = f1[k];
            o0 = fmaf(w.x, a.x, o0); o0 = fmaf(w.y, a.y, o0);
            o0 = fmaf(w.z, a.z, o0); o0 = fmaf(w.w, a.w, o0);
            o1 = fmaf(w.x, b.x, o1); o1 = fmaf(w.y, b.y, o1);
            o1 = fmaf(w.z, b.z, o1); o1 = fmaf(w.w, b.w, o1);
        }
        o0 += __shfl_xor_sync(~0u, o0, 1);
        o1 += __shfl_xor_sync(~0u, o1, 1);
        if (!p) {
            out[(size_t)bg0 * 64 + j] = o0 + head_b[j];
            out[(size_t)bg1 * 64 + j] = o1 + head_b[j];
        }
    }
}

extern "C" void kernel_launch(void* const* d_in, const int* in_sizes, int n_in,
                              void* d_out, int out_size) {
    const int*   seq      = (const int*)  d_in[0];
    const float* memory   = (const float*)d_in[1];
    const float* embed_w  = (const float*)d_in[2];
    const float* w_ih     = (const float*)d_in[3];
    const float* w_hh     = (const float*)d_in[4];
    const float* b_ih     = (const float*)d_in[5];
    const float* b_hh     = (const float*)d_in[6];
    const float* key_w    = (const float*)d_in[7];
    const float* key_b    = (const float*)d_in[8];   // cancels in softmax
    const float* val_w    = (const float*)d_in[9];
    const float* val_b    = (const float*)d_in[10];
    const float* query_w  = (const float*)d_in[11];
    const float* query_b  = (const float*)d_in[12];
    const float* head_w   = (const float*)d_in[13];
    const float* head_b   = (const float*)d_in[14];
    (void)key_b;

    setup_k<<<113, 256>>>(embed_w, w_ih, b_ih, b_hh, key_w, val_w, val_b, query_w, query_b);

    const size_t shmem = (size_t)SMEM_FLOATS * sizeof(float);
    cudaFuncSetAttribute(ffm_kernel, cudaFuncAttributeMaxDynamicSharedMemorySize, (int)shmem);
    ffm_kernel<<<NGRID, NT, shmem>>>(seq, memory, w_hh, b_hh, head_w, head_b, (float*)d_out);
}